// round 2
// baseline (speedup 1.0000x reference)
#include <cuda_runtime.h>

// ---------------- problem constants / scratch ----------------
#define NMAX 1048576
#define HMAX (1 << 19)          // 524288 hash slots (actual H ~ 128000)
#define SCAN_THREADS 1024
#define SCAN_ELEMS 4
#define SCAN_CHUNK (SCAN_THREADS * SCAN_ELEMS)   // 4096
#define SCAN_BLOCKS (HMAX / SCAN_CHUNK)          // 128

// XLA rewrites divide-by-const into multiply-by-reciprocal; 1/0.05f rounds to 20.0f exactly.
#define INV_SIZE 20.0f

__device__ int g_hash[NMAX];
__device__ int g_count[HMAX];
__device__ int g_rank[HMAX];     // exclusive prefix of (count>0): consecutive cluster id
__device__ int g_cursor[HMAX];   // exclusive prefix of count: sort offsets (then bumped)
__device__ int g_sorted[NMAX];
__device__ unsigned long long g_bsum[SCAN_BLOCKS];
__device__ unsigned int g_mm[6]; // encoded min[0..2], max[0..2]

struct Params { float s0, s1, s2; int d0, d01, d012; int b0; };
__device__ Params g_par;

// order-preserving float<->uint encoding for atomic min/max
__device__ __forceinline__ unsigned fenc(float f) {
    unsigned u = __float_as_uint(f);
    return (u & 0x80000000u) ? ~u : (u | 0x80000000u);
}
__device__ __forceinline__ float fdec(unsigned v) {
    return __uint_as_float((v & 0x80000000u) ? (v ^ 0x80000000u) : ~v);
}

// ---------------- kernels ----------------

// zero the whole output (padding rows must be 0; real rows overwritten later),
// zero the histogram, init min/max slots.
__global__ void k_init(float* out, long long out_n) {
    long long i = (long long)blockIdx.x * blockDim.x + threadIdx.x;
    long long stride = (long long)gridDim.x * blockDim.x;
    long long quads = out_n >> 2;
    float4* o4 = (float4*)out;
    float4 z = make_float4(0.f, 0.f, 0.f, 0.f);
    for (long long t = i; t < quads; t += stride) o4[t] = z;
    for (long long t = (quads << 2) + i; t < out_n; t += stride) out[t] = 0.f;
    for (long long t = i; t < HMAX; t += stride) g_count[t] = 0;
    if (i < 3) { g_mm[i] = 0xFFFFFFFFu; g_mm[i + 3] = 0u; }
}

__global__ void k_minmax(const float* __restrict__ pos, int n) {
    int tid = blockIdx.x * blockDim.x + threadIdx.x;
    int stride = gridDim.x * blockDim.x;
    unsigned lmin[3] = {~0u, ~0u, ~0u}, lmax[3] = {0u, 0u, 0u};
    int total = n * 3;
    for (int j = tid; j < total; j += stride) {
        int d = j % 3;
        unsigned e = fenc(pos[j]);
        lmin[d] = min(lmin[d], e);
        lmax[d] = max(lmax[d], e);
    }
    __shared__ unsigned smin[3], smax[3];
    if (threadIdx.x == 0) {
        smin[0] = smin[1] = smin[2] = ~0u;
        smax[0] = smax[1] = smax[2] = 0u;
    }
    __syncthreads();
    #pragma unroll
    for (int d = 0; d < 3; d++) { atomicMin(&smin[d], lmin[d]); atomicMax(&smax[d], lmax[d]); }
    __syncthreads();
    if (threadIdx.x < 3) {
        atomicMin(&g_mm[threadIdx.x], smin[threadIdx.x]);
        atomicMax(&g_mm[3 + threadIdx.x], smax[threadIdx.x]);
    }
}

__global__ void k_params(const int* __restrict__ batch, int n) {
    float s[3], e[3];
    int dims[3];
    #pragma unroll
    for (int d = 0; d < 3; d++) {
        s[d] = fdec(g_mm[d]);
        e[d] = fdec(g_mm[3 + d]);
        // dims = int(floor((end-start) * (1/size)) + 1.0) -- matches XLA's div->mul rewrite
        dims[d] = (int)(floorf(__fmul_rn(__fsub_rn(e[d], s[d]), INV_SIZE)) + 1.0f);
    }
    Params p;
    p.s0 = s[0]; p.s1 = s[1]; p.s2 = s[2];
    p.d0 = dims[0];
    p.d01 = dims[0] * dims[1];
    p.d012 = dims[0] * dims[1] * dims[2];
    p.b0 = batch[0];
    g_par = p;
}

__global__ void k_hash(const float* __restrict__ pos, const int* __restrict__ batch, int n) {
    int i = blockIdx.x * blockDim.x + threadIdx.x;
    if (i >= n) return;
    Params p = g_par;
    float p0 = pos[3 * i + 0], p1 = pos[3 * i + 1], p2 = pos[3 * i + 2];
    int c0 = (int)floorf(__fmul_rn(__fsub_rn(p0, p.s0), INV_SIZE));
    int c1 = (int)floorf(__fmul_rn(__fsub_rn(p1, p.s1), INV_SIZE));
    int c2 = (int)floorf(__fmul_rn(__fsub_rn(p2, p.s2), INV_SIZE));
    int cb = batch[i] - p.b0;   // floor((b - b0) * 1) exact
    int h = c0 + c1 * p.d0 + c2 * p.d01 + cb * p.d012;
    g_hash[i] = h;
    atomicAdd(&g_count[h], 1);
}

// dual prefix sum packed in u64: lo = sum(count), hi = sum(count>0)
__global__ void k_scan1() {
    int base = blockIdx.x * SCAN_CHUNK;
    unsigned long long s = 0;
    for (int t = threadIdx.x; t < SCAN_CHUNK; t += SCAN_THREADS) {
        int c = g_count[base + t];
        s += (unsigned long long)c | ((unsigned long long)(c > 0) << 32);
    }
    __shared__ unsigned long long sh[SCAN_THREADS];
    sh[threadIdx.x] = s;
    __syncthreads();
    for (int off = SCAN_THREADS / 2; off > 0; off >>= 1) {
        if (threadIdx.x < off) sh[threadIdx.x] += sh[threadIdx.x + off];
        __syncthreads();
    }
    if (threadIdx.x == 0) g_bsum[blockIdx.x] = sh[0];
}

__global__ void k_scan2() {   // 1 block, SCAN_BLOCKS threads: exclusive scan of block sums
    __shared__ unsigned long long sh[SCAN_BLOCKS];
    int t = threadIdx.x;
    sh[t] = g_bsum[t];
    __syncthreads();
    unsigned long long own = sh[t];
    for (int off = 1; off < SCAN_BLOCKS; off <<= 1) {
        unsigned long long v = (t >= off) ? sh[t - off] : 0ull;
        __syncthreads();
        sh[t] += v;
        __syncthreads();
    }
    g_bsum[t] = sh[t] - own;  // exclusive (fields don't borrow)
}

__global__ void k_scan3() {
    int base = blockIdx.x * SCAN_CHUNK;
    int t = threadIdx.x;
    int eb = base + t * SCAN_ELEMS;
    int4 cv = *(const int4*)&g_count[eb];
    int c[4] = {cv.x, cv.y, cv.z, cv.w};
    unsigned long long loc[4];
    unsigned long long run = 0;
    #pragma unroll
    for (int j = 0; j < SCAN_ELEMS; j++) {
        loc[j] = run;
        run += (unsigned long long)c[j] | ((unsigned long long)(c[j] > 0) << 32);
    }
    __shared__ unsigned long long sh[SCAN_THREADS];
    sh[t] = run;
    __syncthreads();
    unsigned long long own = run;
    for (int off = 1; off < SCAN_THREADS; off <<= 1) {
        unsigned long long v = (t >= off) ? sh[t - off] : 0ull;
        __syncthreads();
        sh[t] += v;
        __syncthreads();
    }
    unsigned long long pre = g_bsum[blockIdx.x] + (sh[t] - own);
    #pragma unroll
    for (int j = 0; j < SCAN_ELEMS; j++) {
        unsigned long long v = pre + loc[j];
        g_cursor[eb + j] = (int)(v & 0xFFFFFFFFull);
        g_rank[eb + j] = (int)(v >> 32);
    }
}

__global__ void k_scatter(int n) {
    int i = blockIdx.x * blockDim.x + threadIdx.x;
    if (i >= n) return;
    int h = g_hash[i];
    int p = atomicAdd(&g_cursor[h], 1);
    g_sorted[p] = i;
}

// one warp per hash slot: gather max(x) over 64 feats (2 per lane), sum(pos), decode batch
__global__ void k_gather(const float* __restrict__ x, const float* __restrict__ pos,
                         float* __restrict__ out, int n) {
    int gt = blockIdx.x * blockDim.x + threadIdx.x;
    int w = gt >> 5;
    int lane = gt & 31;
    if (w >= HMAX) return;
    int cnt = g_count[w];
    if (cnt == 0) return;
    int end = g_cursor[w];        // after scatter: offset + count
    int beg = end - cnt;
    int k = g_rank[w];

    const float NEG_INF = __int_as_float(0xff800000);
    float2 vmax = make_float2(NEG_INF, NEG_INF);
    float psum = 0.f;
    const float2* x2 = (const float2*)x;
    for (int p = beg; p < end; p++) {
        int idx = g_sorted[p];
        float2 v = x2[(size_t)idx * 32 + lane];
        vmax.x = fmaxf(vmax.x, v.x);
        vmax.y = fmaxf(vmax.y, v.y);
        if (lane < 3) psum += pos[(size_t)idx * 3 + lane];
    }
    ((float2*)out)[(size_t)k * 32 + lane] = vmax;
    if (lane < 3)
        out[(size_t)n * 64 + (size_t)k * 3 + lane] = __fdiv_rn(psum, (float)cnt);
    if (lane == 3) {
        Params pr = g_par;
        int c3 = w / pr.d012;
        out[(size_t)n * 67 + k] = (float)(c3 + pr.b0);
    }
}

// ---------------- launch ----------------
extern "C" void kernel_launch(void* const* d_in, const int* in_sizes, int n_in,
                              void* d_out, int out_size) {
    const float* x = (const float*)d_in[0];
    const float* pos = (const float*)d_in[1];
    const int* batch = (const int*)d_in[2];
    int n = in_sizes[2];
    if (n > NMAX) n = NMAX;
    float* out = (float*)d_out;

    k_init<<<2048, 256>>>(out, (long long)out_size);
    k_minmax<<<512, 256>>>(pos, n);
    k_params<<<1, 1>>>(batch, n);
    int nb = (n + 255) / 256;
    k_hash<<<nb, 256>>>(pos, batch, n);
    k_scan1<<<SCAN_BLOCKS, SCAN_THREADS>>>();
    k_scan2<<<1, SCAN_BLOCKS>>>();
    k_scan3<<<SCAN_BLOCKS, SCAN_THREADS>>>();
    k_scatter<<<nb, 256>>>(n);
    k_gather<<<(HMAX * 32) / 256, 256>>>(x, pos, out, n);
}

// round 3
// speedup vs baseline: 1.2698x; 1.2698x over previous
#include <cuda_runtime.h>

#define NMAX 1048576
#define HMAX (1 << 19)          // 524288 hash slots (actual H ~ 128000)
#define SCAN_THREADS 1024
#define SCAN_ELEMS 4
#define SCAN_CHUNK (SCAN_THREADS * SCAN_ELEMS)   // 4096
#define SCAN_BLOCKS (HMAX / SCAN_CHUNK)          // 128
#define PREP_BLOCKS 2048
#define PREP_THREADS 256

// XLA rewrites divide-by-const into multiply-by-reciprocal; 1/0.05f rounds to 20.0f exactly.
#define INV_SIZE 20.0f

__device__ __align__(16) int g_count[HMAX];
__device__ __align__(16) int g_cursor[HMAX];
__device__ int g_occ[HMAX];      // g_occ[rank] = slot (compacted occupied slots)
__device__ int g_hash[NMAX];
__device__ int g_sorted[NMAX];
__device__ unsigned long long g_bsum[SCAN_BLOCKS];
__device__ unsigned int g_bmm[PREP_BLOCKS * 6];
__device__ int g_ctr0;           // self-resetting ticket counters (start at 0)
__device__ int g_ctr1;
__device__ int g_K;              // number of occupied clusters

struct Params { float s0, s1, s2; int d0, d01, d012; int b0; };
__device__ Params g_par;

// order-preserving float<->uint encoding for min/max
__device__ __forceinline__ unsigned fenc(float f) {
    unsigned u = __float_as_uint(f);
    return (u & 0x80000000u) ? ~u : (u | 0x80000000u);
}
__device__ __forceinline__ float fdec(unsigned v) {
    return __uint_as_float((v & 0x80000000u) ? (v ^ 0x80000000u) : ~v);
}

// streaming zero of float4 range [a,b)
__device__ __forceinline__ void zero_range(float4* o4, long long a, long long b,
                                           long long tid, long long nth) {
    float4 z = make_float4(0.f, 0.f, 0.f, 0.f);
    for (long long t = a + tid; t < b; t += nth) __stcs(&o4[t], z);
}

// ---------------- fused init + minmax + params ----------------
__global__ void k_prep(const float* __restrict__ pos, const int* __restrict__ batch,
                       float4* o4, float* out, long long out_n, int n,
                       long long za, long long zb) {
    long long tid = (long long)blockIdx.x * blockDim.x + threadIdx.x;
    long long nth = (long long)gridDim.x * blockDim.x;

    // zero histogram
    for (long long t = tid; t < HMAX / 4; t += nth)
        ((int4*)g_count)[t] = make_int4(0, 0, 0, 0);
    // zero output share (+ scalar tail of whole output)
    zero_range(o4, za, zb, tid, nth);
    for (long long t = (out_n & ~3LL) + tid; t < out_n; t += nth) out[t] = 0.f;

    // per-thread minmax over points
    unsigned lmin[3] = {~0u, ~0u, ~0u}, lmax[3] = {0u, 0u, 0u};
    for (long long i = tid; i < n; i += nth) {
        #pragma unroll
        for (int d = 0; d < 3; d++) {
            unsigned e = fenc(pos[3 * i + d]);
            lmin[d] = min(lmin[d], e);
            lmax[d] = max(lmax[d], e);
        }
    }
    __shared__ unsigned smin[3], smax[3];
    if (threadIdx.x == 0) {
        smin[0] = smin[1] = smin[2] = ~0u;
        smax[0] = smax[1] = smax[2] = 0u;
    }
    __syncthreads();
    #pragma unroll
    for (int d = 0; d < 3; d++) { atomicMin(&smin[d], lmin[d]); atomicMax(&smax[d], lmax[d]); }
    __syncthreads();
    if (threadIdx.x < 3) {
        g_bmm[blockIdx.x * 6 + threadIdx.x] = smin[threadIdx.x];
        g_bmm[blockIdx.x * 6 + 3 + threadIdx.x] = smax[threadIdx.x];
    }
    __threadfence();
    __shared__ int isLast;
    if (threadIdx.x == 0)
        isLast = (atomicAdd(&g_ctr0, 1) == (int)gridDim.x - 1);
    __syncthreads();
    if (!isLast) return;

    // last block: reduce all block partials, compute params
    unsigned rmin[3] = {~0u, ~0u, ~0u}, rmax[3] = {0u, 0u, 0u};
    for (int b = threadIdx.x; b < PREP_BLOCKS; b += blockDim.x) {
        #pragma unroll
        for (int d = 0; d < 3; d++) {
            rmin[d] = min(rmin[d], g_bmm[b * 6 + d]);
            rmax[d] = max(rmax[d], g_bmm[b * 6 + 3 + d]);
        }
    }
    __syncthreads();
    if (threadIdx.x == 0) {
        smin[0] = smin[1] = smin[2] = ~0u;
        smax[0] = smax[1] = smax[2] = 0u;
    }
    __syncthreads();
    #pragma unroll
    for (int d = 0; d < 3; d++) { atomicMin(&smin[d], rmin[d]); atomicMax(&smax[d], rmax[d]); }
    __syncthreads();
    if (threadIdx.x == 0) {
        int dims[3];
        float s[3];
        #pragma unroll
        for (int d = 0; d < 3; d++) {
            s[d] = fdec(smin[d]);
            float e = fdec(smax[d]);
            dims[d] = (int)(floorf(__fmul_rn(__fsub_rn(e, s[d]), INV_SIZE)) + 1.0f);
        }
        Params p;
        p.s0 = s[0]; p.s1 = s[1]; p.s2 = s[2];
        p.d0 = dims[0];
        p.d01 = dims[0] * dims[1];
        p.d012 = dims[0] * dims[1] * dims[2];
        p.b0 = batch[0];
        g_par = p;
        g_ctr0 = 0;   // reset for next replay
    }
}

// ---------------- hash + histogram (+ zero share) ----------------
__global__ void k_hash(const float* __restrict__ pos, const int* __restrict__ batch, int n,
                       float4* o4, long long za, long long zb) {
    long long tid = (long long)blockIdx.x * blockDim.x + threadIdx.x;
    long long nth = (long long)gridDim.x * blockDim.x;
    zero_range(o4, za, zb, tid, nth);
    int i = (int)tid;
    if (i >= n) return;
    Params p = g_par;
    float p0 = pos[3 * i + 0], p1 = pos[3 * i + 1], p2 = pos[3 * i + 2];
    int c0 = (int)floorf(__fmul_rn(__fsub_rn(p0, p.s0), INV_SIZE));
    int c1 = (int)floorf(__fmul_rn(__fsub_rn(p1, p.s1), INV_SIZE));
    int c2 = (int)floorf(__fmul_rn(__fsub_rn(p2, p.s2), INV_SIZE));
    int cb = batch[i] - p.b0;
    int h = c0 + c1 * p.d0 + c2 * p.d01 + cb * p.d012;
    g_hash[i] = h;
    atomicAdd(&g_count[h], 1);
}

// ---------------- scan pass 1 (block sums) + fused pass 2 in last block ----------------
__global__ void k_scan1(float4* o4, long long za, long long zb) {
    long long tid = (long long)blockIdx.x * blockDim.x + threadIdx.x;
    long long nth = (long long)gridDim.x * blockDim.x;
    zero_range(o4, za, zb, tid, nth);

    int t = threadIdx.x;
    int4 cv = ((const int4*)g_count)[blockIdx.x * SCAN_THREADS + t];
    unsigned long long s =
        (unsigned long long)(unsigned)(cv.x + cv.y + cv.z + cv.w) |
        ((unsigned long long)((cv.x > 0) + (cv.y > 0) + (cv.z > 0) + (cv.w > 0)) << 32);
    __shared__ unsigned long long sh[SCAN_THREADS];
    sh[t] = s;
    __syncthreads();
    for (int off = SCAN_THREADS / 2; off > 0; off >>= 1) {
        if (t < off) sh[t] += sh[t + off];
        __syncthreads();
    }
    if (t == 0) g_bsum[blockIdx.x] = sh[0];
    __threadfence();
    __shared__ int isLast;
    if (t == 0) isLast = (atomicAdd(&g_ctr1, 1) == (int)gridDim.x - 1);
    __syncthreads();
    if (!isLast) return;

    // exclusive scan of SCAN_BLOCKS block sums
    __shared__ unsigned long long sc[SCAN_BLOCKS];
    if (t < SCAN_BLOCKS) sc[t] = g_bsum[t];
    __syncthreads();
    unsigned long long own = (t < SCAN_BLOCKS) ? sc[t] : 0ull;
    for (int off = 1; off < SCAN_BLOCKS; off <<= 1) {
        unsigned long long v = (t >= off && t < SCAN_BLOCKS) ? sc[t - off] : 0ull;
        __syncthreads();
        if (t < SCAN_BLOCKS) sc[t] += v;
        __syncthreads();
    }
    if (t < SCAN_BLOCKS) g_bsum[t] = sc[t] - own;
    if (t == SCAN_BLOCKS - 1) {
        g_K = (int)(sc[t] >> 32);   // total occupied clusters
        g_ctr1 = 0;
    }
}

// ---------------- scan pass 3: per-element prefixes, cursor + compaction ----------------
__global__ void k_scan3(float4* o4, long long za, long long zb) {
    long long tid = (long long)blockIdx.x * blockDim.x + threadIdx.x;
    long long nth = (long long)gridDim.x * blockDim.x;
    zero_range(o4, za, zb, tid, nth);

    int base = blockIdx.x * SCAN_CHUNK;
    int t = threadIdx.x;
    int eb = base + t * SCAN_ELEMS;
    int4 cv = *(const int4*)&g_count[eb];
    int c[4] = {cv.x, cv.y, cv.z, cv.w};
    unsigned long long loc[4];
    unsigned long long run = 0;
    #pragma unroll
    for (int j = 0; j < SCAN_ELEMS; j++) {
        loc[j] = run;
        run += (unsigned long long)c[j] | ((unsigned long long)(c[j] > 0) << 32);
    }
    __shared__ unsigned long long sh[SCAN_THREADS];
    sh[t] = run;
    __syncthreads();
    unsigned long long own = run;
    for (int off = 1; off < SCAN_THREADS; off <<= 1) {
        unsigned long long v = (t >= off) ? sh[t - off] : 0ull;
        __syncthreads();
        sh[t] += v;
        __syncthreads();
    }
    unsigned long long pre = g_bsum[blockIdx.x] + (sh[t] - own);
    #pragma unroll
    for (int j = 0; j < SCAN_ELEMS; j++) {
        unsigned long long v = pre + loc[j];
        g_cursor[eb + j] = (int)(v & 0xFFFFFFFFull);
        if (c[j] > 0) g_occ[(int)(v >> 32)] = eb + j;
    }
}

// ---------------- scatter (counting sort) (+ zero share) ----------------
__global__ void k_scatter(int n, float4* o4, long long za, long long zb) {
    long long tid = (long long)blockIdx.x * blockDim.x + threadIdx.x;
    long long nth = (long long)gridDim.x * blockDim.x;
    zero_range(o4, za, zb, tid, nth);
    int i = (int)tid;
    if (i >= n) return;
    int h = g_hash[i];
    int p = atomicAdd(&g_cursor[h], 1);
    g_sorted[p] = i;
}

// ---------------- gather: persistent, one warp per occupied cluster ----------------
__global__ void k_gather(const float* __restrict__ x, const float* __restrict__ pos,
                         float* __restrict__ out, int n) {
    int lane = threadIdx.x & 31;
    int warp0 = (blockIdx.x * blockDim.x + threadIdx.x) >> 5;
    int nwarps = (gridDim.x * blockDim.x) >> 5;
    int K = g_K;
    Params pr = g_par;
    const float2* x2 = (const float2*)x;
    const float NEG_INF = __int_as_float(0xff800000);

    for (int w = warp0; w < K; w += nwarps) {
        int slot = g_occ[w];
        int cnt = g_count[slot];
        int end = g_cursor[slot];   // after scatter bump: beg + cnt
        int beg = end - cnt;

        float2 vmax = make_float2(NEG_INF, NEG_INF);
        float psum = 0.f;
        for (int b = 0; b < cnt; b += 32) {
            int m = min(cnt - b, 32);
            int idxl = (lane < m) ? g_sorted[beg + b + lane] : 0;
            #pragma unroll 4
            for (int j = 0; j < m; j++) {
                int idx = __shfl_sync(0xffffffffu, idxl, j);
                float2 v = __ldcs(&x2[(size_t)idx * 32 + lane]);
                vmax.x = fmaxf(vmax.x, v.x);
                vmax.y = fmaxf(vmax.y, v.y);
                if (lane < 3) psum += __ldg(&pos[(size_t)idx * 3 + lane]);
            }
        }
        __stcs(&((float2*)out)[(size_t)w * 32 + lane], vmax);
        if (lane < 3)
            out[(size_t)n * 64 + (size_t)w * 3 + lane] = __fdiv_rn(psum, (float)cnt);
        if (lane == 3)
            out[(size_t)n * 67 + w] = (float)(slot / pr.d012 + pr.b0);
    }
}

// ---------------- launch ----------------
extern "C" void kernel_launch(void* const* d_in, const int* in_sizes, int n_in,
                              void* d_out, int out_size) {
    const float* x = (const float*)d_in[0];
    const float* pos = (const float*)d_in[1];
    const int* batch = (const int*)d_in[2];
    int n = in_sizes[2];
    if (n > NMAX) n = NMAX;
    float* out = (float*)d_out;
    float4* o4 = (float4*)d_out;
    long long Q = (long long)out_size >> 2;

    // zero-work shares across latency-bound kernels
    long long q1 = (long long)(Q * 45 / 100);
    long long q2 = (long long)(Q * 65 / 100);
    long long q3 = (long long)(Q * 75 / 100);
    long long q4 = (long long)(Q * 85 / 100);

    int nb = (n + 255) / 256;
    k_prep<<<PREP_BLOCKS, PREP_THREADS>>>(pos, batch, o4, out, (long long)out_size, n, 0, q1);
    k_hash<<<nb, 256>>>(pos, batch, n, o4, q1, q2);
    k_scan1<<<SCAN_BLOCKS, SCAN_THREADS>>>(o4, q2, q3);
    k_scan3<<<SCAN_BLOCKS, SCAN_THREADS>>>(o4, q3, q4);
    k_scatter<<<nb, 256>>>(n, o4, q4, Q);
    k_gather<<<1184, 256>>>(x, pos, out, n);
}